// round 13
// baseline (speedup 1.0000x reference)
#include <cuda_runtime.h>
#include <stdint.h>

// Problem constants (fixed shapes for this problem instance)
#define BB   512          // batch rows
#define DD   3072         // feature dim
#define CC   10           // logit dim
#define NPT  100000       // number of reference points
#define KNN  50           // top-K
#define RPB  8            // rows per block in gather kernel
#define NCHUNK 8          // N chunks in gather kernel
#define CHUNK (NPT / NCHUNK)   // 12500
#define CAP  512          // gather buffer capacity per row (mean ~146, ~12 sigma headroom)
#define SRANK 24          // sample order statistic for threshold
#define NSAMP 16384       // samples per row for threshold (16.4% of N)
#define TTHREADS 512      // threads in k_thresh
#define PREPB ((NPT + 255) / 256)   // 391 blocks for xx/SoA precompute
#define FWARPS 4          // rows (warps) per block in k_final
#define REGN (CAP / 32)   // 16 comb values per lane in k_final

typedef unsigned long long ull;

// ---- device scratch (no runtime allocation allowed) ----
__device__ float        g_logits[BB * CC];
__device__ float        g_ll[BB];
__device__ float        g_maxabs[BB];
__device__ float        g_Tf[BB];          // float-domain threshold
__device__ int          g_cnt[BB];
__device__ float        g_xx[NPT];         // precomputed ||X_i||^2
__device__ float        g_xsoa[CC][NPT];   // X transposed (SoA) -> coalesced loads
__device__ float        g_wt[CC * DD];     // W transposed: WT[j][k] = W[k][j]
__device__ ull          g_comb[BB * CAP];  // packed (key<<18)|(i<<1)|Y per candidate

// monotonic float -> uint mapping (ascending float == ascending uint)
__device__ __forceinline__ unsigned int fkey(float f) {
    unsigned int u = __float_as_uint(f);
    return (u & 0x80000000u) ? ~u : (u | 0x80000000u);
}
// inverse of fkey
__device__ __forceinline__ float ikey(unsigned int v) {
    unsigned int u = (v & 0x80000000u) ? (v & 0x7FFFFFFFu) : ~v;
    return __uint_as_float(u);
}

// ============================================================
// K0: transpose W [DD,CC] -> WT [CC,DD] (one-time 123KB pass).
// ============================================================
__global__ void k_wt(const float* __restrict__ W) {
    int idx = blockIdx.x * 256 + threadIdx.x;   // idx = k*CC + j
    if (idx < DD * CC) {
        int k = idx / CC, j = idx % CC;
        g_wt[j * DD + k] = W[idx];
    }
}

// ============================================================
// K1 (fused front): blocks [0,BB) compute logits = x@WT + b plus
// ||l||^2 and max|l| — all loads coalesced LDG.128.
// Blocks [BB, BB+PREPB) precompute xx[i] and the SoA X transpose.
// ============================================================
__global__ void __launch_bounds__(256)
k_front(const float* __restrict__ x, const float* __restrict__ b,
        const float* __restrict__ Xp, float* __restrict__ out) {
    if (blockIdx.x >= BB) {
        int i = (blockIdx.x - BB) * 256 + threadIdx.x;
        if (i < NPT) {
            const float2* xp = reinterpret_cast<const float2*>(Xp) + (size_t)i * 5;
            float xx = 0.f;
#pragma unroll
            for (int h = 0; h < 5; h++) {
                float2 p = __ldg(xp + h);
                g_xsoa[2 * h][i]     = p.x;
                g_xsoa[2 * h + 1][i] = p.y;
                xx = fmaf(p.x, p.x, xx);
                xx = fmaf(p.y, p.y, xx);
            }
            g_xx[i] = xx;
        }
        return;
    }
    const int row  = blockIdx.x;
    const int tid  = threadIdx.x;
    const int warp = tid >> 5;
    const int lane = tid & 31;
    float acc[CC];
#pragma unroll
    for (int j = 0; j < CC; j++) acc[j] = 0.f;
    const float4* xr = reinterpret_cast<const float4*>(x + (size_t)row * DD);
#pragma unroll
    for (int m = 0; m < 3; m++) {
        const int k4 = tid + 256 * m;            // < 768 = DD/4
        float4 xv = __ldg(xr + k4);
#pragma unroll
        for (int j = 0; j < CC; j++) {
            float4 w4 = __ldg(reinterpret_cast<const float4*>(g_wt + j * DD) + k4);
            acc[j] = fmaf(xv.x, w4.x,
                     fmaf(xv.y, w4.y,
                     fmaf(xv.z, w4.z,
                     fmaf(xv.w, w4.w, acc[j]))));
        }
    }
    __shared__ float part[8][CC];
#pragma unroll
    for (int j = 0; j < CC; j++) {
#pragma unroll
        for (int o = 16; o > 0; o >>= 1)
            acc[j] += __shfl_down_sync(0xffffffffu, acc[j], o);
        if (lane == 0) part[warp][j] = acc[j];
    }
    __syncthreads();
    if (tid == 0) {
        float ll = 0.f, ma = 0.f;
#pragma unroll
        for (int j = 0; j < CC; j++) {
            float v = b[j];
#pragma unroll
            for (int w = 0; w < 8; w++) v += part[w][j];
            g_logits[row * CC + j] = v;
            out[row * 11 + j] = v;
            ll = fmaf(v, v, ll);
            ma = fmaxf(ma, fabsf(v));
        }
        g_ll[row] = ll;
        g_maxabs[row] = ma;
    }
}

// ============================================================
// K2: per-row conservative threshold, one row/block, SoA
// coalesced X loads. 16384 samples as 512 groups of 32
// consecutive points. T = 24th smallest sampled key; true
// count(key<=T): mean ~146, sigma ~30.
// Scalar fmaf chain ascending j — IDENTICAL chain to k_gather.
// Zeroes the row's counter.
// ============================================================
__global__ void __launch_bounds__(TTHREADS, 1)
k_thresh() {
    const int row  = blockIdx.x;
    const int tid  = threadIdx.x;
    const int warp = tid >> 5;        // 0..15
    const int lane = tid & 31;
    if (tid == 0) g_cnt[row] = 0;
    float lg[CC];
#pragma unroll
    for (int j = 0; j < CC; j++) lg[j] = g_logits[row * CC + j];
    const float ll = g_ll[row];

    unsigned int keys[NSAMP / TTHREADS];          // 32 per thread
#pragma unroll
    for (int u = 0; u < NSAMP / TTHREADS; u++) {
        int g = warp + 16 * u;                                   // 0..511 groups
        int i = (int)(((long long)g * NPT) >> 9) + lane;         // 32 consecutive points
        float dot = 0.f;
#pragma unroll
        for (int j = 0; j < CC; j++)
            dot = fmaf(lg[j], __ldg(&g_xsoa[j][i]), dot);
        // (ll - 2*dot): FFMA(-2,dot,ll) or FMUL+FADD are bit-equal (2*dot exact)
        float key = (ll - 2.0f * dot) + __ldg(&g_xx[i]);
        keys[u] = fkey(key);
    }

    __shared__ int scnt[32];
    if (tid < 32) scnt[tid] = 0;
    __syncthreads();
    unsigned int lo = 0u, hi = 0xFFFFFFFFu;
    for (int it = 0; it < 32; it++) {
        unsigned int mid = lo + ((hi - lo) >> 1);
        int c = 0;
#pragma unroll
        for (int u = 0; u < NSAMP / TTHREADS; u++) c += (keys[u] <= mid) ? 1 : 0;
        for (int o = 16; o > 0; o >>= 1) c += __shfl_down_sync(0xffffffffu, c, o);
        if (lane == 0) atomicAdd(&scnt[it], c);
        __syncthreads();
        if (scnt[it] >= SRANK) hi = mid; else lo = mid + 1;
    }
    if (tid == 0) g_Tf[row] = ikey(lo);   // an actual sampled key -> finite
}

// ============================================================
// K3: fused distance + gather — SCALAR FMA version (the
// decisive spill experiment). Register audit: lg[8][10] f32 =
// 80 + xv[10] + Tf[8] + ll[8] + loop/misc ~= 115 regs -> fits
// the 128-reg cap with NO spill possible (the f32x2 version
// needed ~140 in aligned even/odd pairs -> LDL replay, the
// suspected cause of the steady ~130us). 8 independent FMA
// chains give ample ILP. Chain per row is the scalar
// ascending-j fmaf chain -> bit-identical to k_thresh.
// 64 groups x 8 chunks = 512 blocks.
// ============================================================
__global__ void __launch_bounds__(256, 1)
k_gather(const int* __restrict__ Y) {
    const int group = blockIdx.x >> 3;        // / NCHUNK
    const int chunk = blockIdx.x & 7;         // % NCHUNK
    const int r0 = group * RPB;

    float lg[RPB][CC], ll[RPB], Tf[RPB];
#pragma unroll
    for (int r = 0; r < RPB; r++) {
#pragma unroll
        for (int j = 0; j < CC; j++) lg[r][j] = g_logits[(r0 + r) * CC + j];
        ll[r] = g_ll[r0 + r];
        Tf[r] = g_Tf[r0 + r];
    }

    const int base = chunk * CHUNK;
    for (int i0 = threadIdx.x; i0 < CHUNK; i0 += 256) {
        const int i = base + i0;
        float xv[CC];
#pragma unroll
        for (int j = 0; j < CC; j++) xv[j] = __ldg(&g_xsoa[j][i]);
        const float xx = __ldg(&g_xx[i]);

#pragma unroll
        for (int r = 0; r < RPB; r++) {
            float dot = 0.f;
#pragma unroll
            for (int j = 0; j < CC; j++) dot = fmaf(lg[r][j], xv[j], dot);
            float key = (ll[r] - 2.0f * dot) + xx;
            if (key <= Tf[r]) {
                int row = r0 + r;
                int pos = atomicAdd(&g_cnt[row], 1);
                if (pos < CAP)
                    g_comb[row * CAP + pos] =
                        (((ull)fkey(key)) << 18) | (ull)((i << 1) | Y[i]);
            }
        }
    }
}

// ============================================================
// K4: exact top-K, one warp per row, register-resident.
// 32-iter binary search over the 32-bit KEY, then exact tie
// resolution (jax lower-index-first) via reduce-min over the
// (usually size-1) tie group. Identical selection to a 50-bit
// search with shorter critical path. 4 warps/block.
// ============================================================
__global__ void __launch_bounds__(32 * FWARPS, 1)
k_final(float* __restrict__ out) {
    const int w    = threadIdx.x >> 5;
    const int lane = threadIdx.x & 31;
    const int row  = blockIdx.x * FWARPS + w;

    int n = g_cnt[row];
    if (n > CAP) n = CAP;

    ull comb[REGN];
    unsigned int key[REGN];
#pragma unroll
    for (int r = 0; r < REGN; r++) {
        int t = lane + 32 * r;
        comb[r] = (t < n) ? __ldg(&g_comb[row * CAP + t]) : ~0ull;
        key[r]  = (unsigned int)(comb[r] >> 18);   // pad -> 0xFFFFFFFF (never selected)
    }

    // 32-iter binary search: smallest key value with count(<=) >= KNN
    unsigned int lo = 0u, hi = 0xFFFFFFFFu;
    for (int it = 0; it < 32; it++) {
        unsigned int mid = lo + ((hi - lo) >> 1);
        unsigned int c = 0;
#pragma unroll
        for (int r = 0; r < REGN; r++) c += (key[r] <= mid) ? 1u : 0u;
        c = __reduce_add_sync(0xffffffffu, c);
        if (c >= KNN) hi = mid; else lo = mid + 1;
    }
    const unsigned int cut = lo;

    // strictly-below counts and Y-sum
    unsigned int cless = 0, ones = 0;
#pragma unroll
    for (int r = 0; r < REGN; r++) {
        if (key[r] < cut) {
            cless++;
            ones += (unsigned int)(comb[r] & 1ull);
        }
    }
    cless = __reduce_add_sync(0xffffffffu, cless);
    ones  = __reduce_add_sync(0xffffffffu, ones);
    int m = KNN - (int)cless;                 // >= 1 members taken from tie group

    // tie group: key == cut; take the m smallest ((i<<1)|Y) (== idx order;
    // idx values are globally distinct, so each reduce-min has a unique owner)
    unsigned int tieMask = 0;
#pragma unroll
    for (int r = 0; r < REGN; r++)
        if (key[r] == cut) tieMask |= (1u << r);
    for (int t = 0; t < m; t++) {
        unsigned int myMin = 0x7FFFFFFFu;
        int myR = -1;
#pragma unroll
        for (int r = 0; r < REGN; r++) {
            if ((tieMask >> r) & 1u) {
                unsigned int v = (unsigned int)(comb[r] & 0x3FFFFull);
                if (v < myMin) { myMin = v; myR = r; }
            }
        }
        unsigned int gmin = __reduce_min_sync(0xffffffffu, myMin);
        ones += gmin & 1u;                    // Y bit of selected element (warp-uniform)
        if (myMin == gmin && myR >= 0) tieMask &= ~(1u << myR);
    }

    if (lane == 0) {
        float v = (float)(2 * (int)ones - KNN);
        float s = (v > 0.f) ? 1.f : ((v < 0.f) ? -1.f : 0.f);
        out[row * 11 + 10] = s * 2.0f * g_maxabs[row];
    }
}

// ============================================================
extern "C" void kernel_launch(void* const* d_in, const int* in_sizes, int n_in,
                              void* d_out, int out_size) {
    const float* x = (const float*)d_in[0];
    const float* W = (const float*)d_in[1];
    const float* b = (const float*)d_in[2];
    const float* X = (const float*)d_in[3];
    const int*   Y = (const int*)d_in[4];
    float* out = (float*)d_out;

    k_wt<<<(DD * CC + 255) / 256, 256>>>(W);
    k_front<<<BB + PREPB, 256>>>(x, b, X, out);
    k_thresh<<<BB, TTHREADS>>>();
    k_gather<<<(BB / RPB) * NCHUNK, 256>>>(Y);
    k_final<<<BB / FWARPS, 32 * FWARPS>>>(out);
}

// round 14
// speedup vs baseline: 1.0470x; 1.0470x over previous
#include <cuda_runtime.h>
#include <stdint.h>

// Problem constants (fixed shapes for this problem instance)
#define BB   512          // batch rows
#define DD   3072         // feature dim
#define CC   10           // logit dim
#define NPT  100000       // number of reference points
#define KNN  50           // top-K
#define RPB  16           // rows per block in gather kernel
#define NCHUNK 16         // N chunks in gather kernel
#define CHUNK (NPT / NCHUNK)   // 6250
#define CAP  512          // gather buffer capacity per row (mean ~146, ~12 sigma headroom)
#define SRANK 24          // sample order statistic for threshold
#define NSAMP 16384       // samples per row for threshold (16.4% of N)
#define TTHREADS 512      // threads in k_thresh
#define PREPB ((NPT + 255) / 256)   // 391 blocks for xx/SoA precompute
#define FWARPS 4          // rows (warps) per block in k_final
#define REGN (CAP / 32)   // 16 comb values per lane in k_final

typedef unsigned long long ull;

// ---- device scratch (no runtime allocation allowed) ----
__device__ float        g_logits[BB * CC];
__device__ float        g_ll[BB];
__device__ float        g_maxabs[BB];
__device__ float        g_Tf[BB];          // float-domain threshold
__device__ int          g_cnt[BB];
__device__ float        g_xx[NPT];         // precomputed ||X_i||^2
__device__ float        g_xsoa[CC][NPT];   // X transposed (SoA) -> coalesced loads
__device__ ull          g_comb[BB * CAP];  // packed (key<<18)|(i<<1)|Y per candidate

// monotonic float -> uint mapping (ascending float == ascending uint)
__device__ __forceinline__ unsigned int fkey(float f) {
    unsigned int u = __float_as_uint(f);
    return (u & 0x80000000u) ? ~u : (u | 0x80000000u);
}
// inverse of fkey
__device__ __forceinline__ float ikey(unsigned int v) {
    unsigned int u = (v & 0x80000000u) ? (v & 0x7FFFFFFFu) : ~v;
    return __uint_as_float(u);
}

// ============================================================
// K1 (fused front — EXACT r7-measured version, plus SoA stores
// in the prep half): blocks [0,BB) compute logits = x@W + b,
// ||l||^2, max|l| (warp-shfl reduction, one barrier); blocks
// [BB, BB+PREPB) precompute xx[i] and the X SoA transpose.
// ============================================================
__global__ void __launch_bounds__(256)
k_front(const float* __restrict__ x, const float* __restrict__ W,
        const float* __restrict__ b, const float* __restrict__ Xp,
        float* __restrict__ out) {
    if (blockIdx.x >= BB) {
        int i = (blockIdx.x - BB) * 256 + threadIdx.x;
        if (i < NPT) {
            const float2* xp = reinterpret_cast<const float2*>(Xp) + (size_t)i * 5;
            float xx = 0.f;
#pragma unroll
            for (int h = 0; h < 5; h++) {
                float2 p = __ldg(xp + h);
                g_xsoa[2 * h][i]     = p.x;
                g_xsoa[2 * h + 1][i] = p.y;
                xx = fmaf(p.x, p.x, xx);
                xx = fmaf(p.y, p.y, xx);
            }
            g_xx[i] = xx;
        }
        return;
    }
    const int row  = blockIdx.x;
    const int tid  = threadIdx.x;
    const int warp = tid >> 5;
    const int lane = tid & 31;
    float acc[CC];
#pragma unroll
    for (int j = 0; j < CC; j++) acc[j] = 0.f;
    const float4* xr = reinterpret_cast<const float4*>(x + (size_t)row * DD);
    for (int k4 = tid; k4 < DD / 4; k4 += 256) {
        float4 xv = __ldg(xr + k4);
        float xs[4] = {xv.x, xv.y, xv.z, xv.w};
#pragma unroll
        for (int q = 0; q < 4; q++) {
            const float2* wr = reinterpret_cast<const float2*>(W + (size_t)(k4 * 4 + q) * CC);
#pragma unroll
            for (int h = 0; h < 5; h++) {
                float2 w2 = __ldg(wr + h);
                acc[2 * h]     = fmaf(xs[q], w2.x, acc[2 * h]);
                acc[2 * h + 1] = fmaf(xs[q], w2.y, acc[2 * h + 1]);
            }
        }
    }
    __shared__ float part[8][CC];
#pragma unroll
    for (int j = 0; j < CC; j++) {
#pragma unroll
        for (int o = 16; o > 0; o >>= 1)
            acc[j] += __shfl_down_sync(0xffffffffu, acc[j], o);
        if (lane == 0) part[warp][j] = acc[j];
    }
    __syncthreads();
    if (tid == 0) {
        float ll = 0.f, ma = 0.f;
#pragma unroll
        for (int j = 0; j < CC; j++) {
            float v = b[j];
#pragma unroll
            for (int w = 0; w < 8; w++) v += part[w][j];
            g_logits[row * CC + j] = v;
            out[row * 11 + j] = v;
            ll = fmaf(v, v, ll);
            ma = fmaxf(ma, fabsf(v));
        }
        g_ll[row] = ll;
        g_maxabs[row] = ma;
    }
}

// ============================================================
// K2 (EXACT r7-measured version): per-row threshold via
// deterministic sampling, 16384 samples/row as 512 groups of 32
// consecutive points. T = 24th smallest sampled key; true-data
// count(key<=T): mean ~146, sigma ~30. Scalar ascending-j fmaf
// chain — bit-identical to k_gather's. Zeroes the row counter.
// ============================================================
__global__ void __launch_bounds__(TTHREADS)
k_thresh(const float* __restrict__ Xp) {
    const int row  = blockIdx.x;
    const int tid  = threadIdx.x;
    const int warp = tid >> 5;        // 0..15
    const int lane = tid & 31;
    if (tid == 0) g_cnt[row] = 0;
    float lg[CC];
#pragma unroll
    for (int j = 0; j < CC; j++) lg[j] = g_logits[row * CC + j];
    const float ll = g_ll[row];

    unsigned int keys[NSAMP / TTHREADS];          // 32 per thread
#pragma unroll
    for (int u = 0; u < NSAMP / TTHREADS; u++) {
        int g = warp + 16 * u;                                   // 0..511 groups
        int i = (int)(((long long)g * NPT) >> 9) + lane;         // 32 consecutive points
        const float2* xp = reinterpret_cast<const float2*>(Xp) + (size_t)i * 5;
        float dot = 0.f;
#pragma unroll
        for (int h = 0; h < 5; h++) {
            float2 p = __ldg(xp + h);
            dot = fmaf(lg[2 * h],     p.x, dot);
            dot = fmaf(lg[2 * h + 1], p.y, dot);
        }
        // (ll - 2*dot): FFMA(-2,dot,ll) or FMUL+FADD are bit-equal (2*dot exact)
        float key = (ll - 2.0f * dot) + __ldg(&g_xx[i]);
        keys[u] = fkey(key);
    }

    __shared__ int scnt[32];
    if (tid < 32) scnt[tid] = 0;
    __syncthreads();
    unsigned int lo = 0u, hi = 0xFFFFFFFFu;
    for (int it = 0; it < 32; it++) {
        unsigned int mid = lo + ((hi - lo) >> 1);
        int c = 0;
#pragma unroll
        for (int u = 0; u < NSAMP / TTHREADS; u++) c += (keys[u] <= mid) ? 1 : 0;
        for (int o = 16; o > 0; o >>= 1) c += __shfl_down_sync(0xffffffffu, c, o);
        if (lane == 0) atomicAdd(&scnt[it], c);
        __syncthreads();
        if (scnt[it] >= SRANK) hi = mid; else lo = mid + 1;
    }
    if (tid == 0) g_Tf[row] = ikey(lo);   // an actual sampled key -> finite
}

// ============================================================
// K3: fused distance + gather — RPB=16 (the latency fix).
// Profile r13 (RPB=8): 122.8us, occ 11.8%, issue 26.9% -> each
// 11-load batch fed only 160 FMAs; with 2 warps/SMSP the ~250cyc
// L2 latency was exposed. RPB=16 doubles compute per load batch
// (320 FMAs/warp between stalls) AND halves X L2 traffic
// (141MB, ~11us floor). Regs ~215 pinned by (256,1); 8 warps/SM.
// Chain per row is the scalar ascending-j fmaf chain ->
// bit-identical to k_thresh. 32 groups x 16 chunks = 512 blocks.
// ============================================================
__global__ void __launch_bounds__(256, 1)
k_gather(const int* __restrict__ Y) {
    const int group = blockIdx.x >> 4;        // / NCHUNK
    const int chunk = blockIdx.x & 15;        // % NCHUNK
    const int r0 = group * RPB;

    float lg[RPB][CC], ll[RPB], Tf[RPB];
#pragma unroll
    for (int r = 0; r < RPB; r++) {
#pragma unroll
        for (int j = 0; j < CC; j++) lg[r][j] = g_logits[(r0 + r) * CC + j];
        ll[r] = g_ll[r0 + r];
        Tf[r] = g_Tf[r0 + r];
    }

    const int base = chunk * CHUNK;
    for (int i0 = threadIdx.x; i0 < CHUNK; i0 += 256) {
        const int i = base + i0;
        float xv[CC];
#pragma unroll
        for (int j = 0; j < CC; j++) xv[j] = __ldg(&g_xsoa[j][i]);
        const float xx = __ldg(&g_xx[i]);

#pragma unroll
        for (int r = 0; r < RPB; r++) {
            float dot = 0.f;
#pragma unroll
            for (int j = 0; j < CC; j++) dot = fmaf(lg[r][j], xv[j], dot);
            float key = (ll[r] - 2.0f * dot) + xx;
            if (key <= Tf[r]) {
                int row = r0 + r;
                int pos = atomicAdd(&g_cnt[row], 1);
                if (pos < CAP)
                    g_comb[row * CAP + pos] =
                        (((ull)fkey(key)) << 18) | (ull)((i << 1) | Y[i]);
            }
        }
    }
}

// ============================================================
// K4: exact top-K, one warp per row, register-resident.
// 32-iter binary search over the 32-bit KEY, then exact tie
// resolution (jax lower-index-first) via reduce-min over the
// (usually size-1) tie group. 4 warps/block.
// ============================================================
__global__ void __launch_bounds__(32 * FWARPS, 1)
k_final(float* __restrict__ out) {
    const int w    = threadIdx.x >> 5;
    const int lane = threadIdx.x & 31;
    const int row  = blockIdx.x * FWARPS + w;

    int n = g_cnt[row];
    if (n > CAP) n = CAP;

    ull comb[REGN];
    unsigned int key[REGN];
#pragma unroll
    for (int r = 0; r < REGN; r++) {
        int t = lane + 32 * r;
        comb[r] = (t < n) ? __ldg(&g_comb[row * CAP + t]) : ~0ull;
        key[r]  = (unsigned int)(comb[r] >> 18);   // pad -> 0xFFFFFFFF (never selected)
    }

    // 32-iter binary search: smallest key value with count(<=) >= KNN
    unsigned int lo = 0u, hi = 0xFFFFFFFFu;
    for (int it = 0; it < 32; it++) {
        unsigned int mid = lo + ((hi - lo) >> 1);
        unsigned int c = 0;
#pragma unroll
        for (int r = 0; r < REGN; r++) c += (key[r] <= mid) ? 1u : 0u;
        c = __reduce_add_sync(0xffffffffu, c);
        if (c >= KNN) hi = mid; else lo = mid + 1;
    }
    const unsigned int cut = lo;

    // strictly-below counts and Y-sum
    unsigned int cless = 0, ones = 0;
#pragma unroll
    for (int r = 0; r < REGN; r++) {
        if (key[r] < cut) {
            cless++;
            ones += (unsigned int)(comb[r] & 1ull);
        }
    }
    cless = __reduce_add_sync(0xffffffffu, cless);
    ones  = __reduce_add_sync(0xffffffffu, ones);
    int m = KNN - (int)cless;                 // >= 1 members taken from tie group

    // tie group: key == cut; take the m smallest ((i<<1)|Y) (== idx order;
    // idx values are globally distinct, so each reduce-min has a unique owner)
    unsigned int tieMask = 0;
#pragma unroll
    for (int r = 0; r < REGN; r++)
        if (key[r] == cut) tieMask |= (1u << r);
    for (int t = 0; t < m; t++) {
        unsigned int myMin = 0x7FFFFFFFu;
        int myR = -1;
#pragma unroll
        for (int r = 0; r < REGN; r++) {
            if ((tieMask >> r) & 1u) {
                unsigned int v = (unsigned int)(comb[r] & 0x3FFFFull);
                if (v < myMin) { myMin = v; myR = r; }
            }
        }
        unsigned int gmin = __reduce_min_sync(0xffffffffu, myMin);
        ones += gmin & 1u;                    // Y bit of selected element (warp-uniform)
        if (myMin == gmin && myR >= 0) tieMask &= ~(1u << myR);
    }

    if (lane == 0) {
        float v = (float)(2 * (int)ones - KNN);
        float s = (v > 0.f) ? 1.f : ((v < 0.f) ? -1.f : 0.f);
        out[row * 11 + 10] = s * 2.0f * g_maxabs[row];
    }
}

// ============================================================
extern "C" void kernel_launch(void* const* d_in, const int* in_sizes, int n_in,
                              void* d_out, int out_size) {
    const float* x = (const float*)d_in[0];
    const float* W = (const float*)d_in[1];
    const float* b = (const float*)d_in[2];
    const float* X = (const float*)d_in[3];
    const int*   Y = (const int*)d_in[4];
    float* out = (float*)d_out;

    k_front<<<BB + PREPB, 256>>>(x, W, b, X, out);
    k_thresh<<<BB, TTHREADS>>>(X);
    k_gather<<<(BB / RPB) * NCHUNK, 256>>>(Y);
    k_final<<<BB / FWARPS, 32 * FWARPS>>>(out);
}

// round 16
// speedup vs baseline: 1.1159x; 1.0658x over previous
#include <cuda_runtime.h>
#include <stdint.h>

// Problem constants (fixed shapes for this problem instance)
#define BB   512          // batch rows
#define DD   3072         // feature dim
#define CC   10           // logit dim
#define NPT  100000       // number of reference points
#define KNN  50           // top-K
#define RPB  8            // rows per block in gather kernel
#define NCHUNK 8          // N chunks in gather kernel
#define CHUNK (NPT / NCHUNK)   // 12500
#define IPT  4            // points per thread per pass in gather (MLP amortization)
#define CAP  512          // gather buffer capacity per row (mean ~146, ~12 sigma headroom)
#define SRANK 24          // sample order statistic for threshold
#define NSAMP 16384       // samples per row for threshold (16.4% of N)
#define TTHREADS 512      // threads in k_thresh
#define PREPB ((NPT + 255) / 256)   // 391 blocks for xx/pack precompute
#define FWARPS 4          // rows (warps) per block in k_final
#define REGN (CAP / 32)   // 16 comb values per lane in k_final

typedef unsigned long long ull;

// ---- device scratch (no runtime allocation allowed) ----
__device__ float        g_logits[BB * CC];
__device__ float        g_ll[BB];
__device__ float        g_maxabs[BB];
__device__ float        g_Tf[BB];          // float-domain threshold
__device__ int          g_cnt[BB];
__device__ float        g_xx[NPT];         // precomputed ||X_i||^2
__device__ float4       g_xq0[NPT];        // X[i][0..3]  packed
__device__ float4       g_xq1[NPT];        // X[i][4..7]  packed
__device__ float2       g_xq2[NPT];        // X[i][8..9]  packed
__device__ ull          g_comb[BB * CAP];  // packed (key<<18)|(i<<1)|Y per candidate

// monotonic float -> uint mapping (ascending float == ascending uint)
__device__ __forceinline__ unsigned int fkey(float f) {
    unsigned int u = __float_as_uint(f);
    return (u & 0x80000000u) ? ~u : (u | 0x80000000u);
}
// inverse of fkey
__device__ __forceinline__ float ikey(unsigned int v) {
    unsigned int u = (v & 0x80000000u) ? (v & 0x7FFFFFFFu) : ~v;
    return __uint_as_float(u);
}

// load X point i into xv[0..9] with exactly 3 wide loads
__device__ __forceinline__ void load_point(int i, float* xv) {
    float4 a = __ldg(&g_xq0[i]);
    float4 c = __ldg(&g_xq1[i]);
    float2 e = __ldg(&g_xq2[i]);
    xv[0] = a.x; xv[1] = a.y; xv[2] = a.z; xv[3] = a.w;
    xv[4] = c.x; xv[5] = c.y; xv[6] = c.z; xv[7] = c.w;
    xv[8] = e.x; xv[9] = e.y;
}

// ============================================================
// K1 (fused front — r7-measured logits half + pack prep):
// blocks [0,BB) compute logits = x@W + b, ||l||^2, max|l|;
// blocks [BB, BB+PREPB) precompute xx[i] and the packed
// float4/float2 X layout (4 loads/point downstream vs 11).
// ============================================================
__global__ void __launch_bounds__(256)
k_front(const float* __restrict__ x, const float* __restrict__ W,
        const float* __restrict__ b, const float* __restrict__ Xp,
        float* __restrict__ out) {
    if (blockIdx.x >= BB) {
        int i = (blockIdx.x - BB) * 256 + threadIdx.x;
        if (i < NPT) {
            const float2* xp = reinterpret_cast<const float2*>(Xp) + (size_t)i * 5;
            float2 p0 = __ldg(xp + 0), p1 = __ldg(xp + 1), p2 = __ldg(xp + 2),
                   p3 = __ldg(xp + 3), p4 = __ldg(xp + 4);
            g_xq0[i] = make_float4(p0.x, p0.y, p1.x, p1.y);
            g_xq1[i] = make_float4(p2.x, p2.y, p3.x, p3.y);
            g_xq2[i] = make_float2(p4.x, p4.y);
            float xx = 0.f;
            xx = fmaf(p0.x, p0.x, xx); xx = fmaf(p0.y, p0.y, xx);
            xx = fmaf(p1.x, p1.x, xx); xx = fmaf(p1.y, p1.y, xx);
            xx = fmaf(p2.x, p2.x, xx); xx = fmaf(p2.y, p2.y, xx);
            xx = fmaf(p3.x, p3.x, xx); xx = fmaf(p3.y, p3.y, xx);
            xx = fmaf(p4.x, p4.x, xx); xx = fmaf(p4.y, p4.y, xx);
            g_xx[i] = xx;
        }
        return;
    }
    const int row  = blockIdx.x;
    const int tid  = threadIdx.x;
    const int warp = tid >> 5;
    const int lane = tid & 31;
    float acc[CC];
#pragma unroll
    for (int j = 0; j < CC; j++) acc[j] = 0.f;
    const float4* xr = reinterpret_cast<const float4*>(x + (size_t)row * DD);
    for (int k4 = tid; k4 < DD / 4; k4 += 256) {
        float4 xv = __ldg(xr + k4);
        float xs[4] = {xv.x, xv.y, xv.z, xv.w};
#pragma unroll
        for (int q = 0; q < 4; q++) {
            const float2* wr = reinterpret_cast<const float2*>(W + (size_t)(k4 * 4 + q) * CC);
#pragma unroll
            for (int h = 0; h < 5; h++) {
                float2 w2 = __ldg(wr + h);
                acc[2 * h]     = fmaf(xs[q], w2.x, acc[2 * h]);
                acc[2 * h + 1] = fmaf(xs[q], w2.y, acc[2 * h + 1]);
            }
        }
    }
    __shared__ float part[8][CC];
#pragma unroll
    for (int j = 0; j < CC; j++) {
#pragma unroll
        for (int o = 16; o > 0; o >>= 1)
            acc[j] += __shfl_down_sync(0xffffffffu, acc[j], o);
        if (lane == 0) part[warp][j] = acc[j];
    }
    __syncthreads();
    if (tid == 0) {
        float ll = 0.f, ma = 0.f;
#pragma unroll
        for (int j = 0; j < CC; j++) {
            float v = b[j];
#pragma unroll
            for (int w = 0; w < 8; w++) v += part[w][j];
            g_logits[row * CC + j] = v;
            out[row * 11 + j] = v;
            ll = fmaf(v, v, ll);
            ma = fmaxf(ma, fabsf(v));
        }
        g_ll[row] = ll;
        g_maxabs[row] = ma;
    }
}

// ============================================================
// K2: per-row threshold via deterministic sampling with the
// packed 4-load point access. 16384 samples/row as 512 groups
// of 32 consecutive points. T = 24th smallest sampled key;
// true-data count(key<=T): mean ~146, sigma ~30.
// Scalar ascending-j fmaf chain — bit-identical to k_gather's.
// Zeroes the row counter.
// ============================================================
__global__ void __launch_bounds__(TTHREADS)
k_thresh() {
    const int row  = blockIdx.x;
    const int tid  = threadIdx.x;
    const int warp = tid >> 5;        // 0..15
    const int lane = tid & 31;
    if (tid == 0) g_cnt[row] = 0;
    float lg[CC];
#pragma unroll
    for (int j = 0; j < CC; j++) lg[j] = g_logits[row * CC + j];
    const float ll = g_ll[row];

    unsigned int keys[NSAMP / TTHREADS];          // 32 per thread
#pragma unroll
    for (int u = 0; u < NSAMP / TTHREADS; u++) {
        int g = warp + 16 * u;                                   // 0..511 groups
        int i = (int)(((long long)g * NPT) >> 9) + lane;         // 32 consecutive points
        float xv[CC];
        load_point(i, xv);
        float dot = 0.f;
#pragma unroll
        for (int j = 0; j < CC; j++) dot = fmaf(lg[j], xv[j], dot);
        // (ll - 2*dot): FFMA(-2,dot,ll) or FMUL+FADD are bit-equal (2*dot exact)
        float key = (ll - 2.0f * dot) + __ldg(&g_xx[i]);
        keys[u] = fkey(key);
    }

    __shared__ int scnt[32];
    if (tid < 32) scnt[tid] = 0;
    __syncthreads();
    unsigned int lo = 0u, hi = 0xFFFFFFFFu;
    for (int it = 0; it < 32; it++) {
        unsigned int mid = lo + ((hi - lo) >> 1);
        int c = 0;
#pragma unroll
        for (int u = 0; u < NSAMP / TTHREADS; u++) c += (keys[u] <= mid) ? 1 : 0;
        for (int o = 16; o > 0; o >>= 1) c += __shfl_down_sync(0xffffffffu, c, o);
        if (lane == 0) atomicAdd(&scnt[it], c);
        __syncthreads();
        if (scnt[it] >= SRANK) hi = mid; else lo = mid + 1;
    }
    if (tid == 0) g_Tf[row] = ikey(lo);   // an actual sampled key -> finite
}

// ============================================================
// K3: fused distance + gather — RPB=8, IPT=4, packed 4-load
// points (the combined MLP fix).
// r13 measured binder: occ 11.8%, issue 26.9%, memory idle —
// warps exposed ~250cyc L2 latency per 11-load batch with ~120
// instr of cover. Now: 16 wide loads per 4-point pass (64cyc
// LSU floor) feeding ~340 FMA-class instr; with 2 warps/SMSP
// the latency window is fully covered. Regs ~145 (lg 80 + xv 40
// + misc) under the (256,1) budget -> no spill (r13 shape ran
// 139 regs spill-free). Per-point chain is the scalar
// ascending-j fmaf chain -> bit-identical to k_thresh.
// 64 groups x 8 chunks = 512 blocks.
// ============================================================
__global__ void __launch_bounds__(256, 1)
k_gather(const int* __restrict__ Y) {
    const int group = blockIdx.x >> 3;        // / NCHUNK
    const int chunk = blockIdx.x & 7;         // % NCHUNK
    const int r0 = group * RPB;

    float lg[RPB][CC], ll[RPB], Tf[RPB];
#pragma unroll
    for (int r = 0; r < RPB; r++) {
#pragma unroll
        for (int j = 0; j < CC; j++) lg[r][j] = g_logits[(r0 + r) * CC + j];
        ll[r] = g_ll[r0 + r];
        Tf[r] = g_Tf[r0 + r];
    }

    const int base = chunk * CHUNK;
    for (int i0 = threadIdx.x; i0 < CHUNK; i0 += 256 * IPT) {
        // ---- load phase: 4 points x 4 wide loads, all issued before use ----
        float xv[IPT][CC], xx[IPT];
        bool  ok[IPT];
        int   ii[IPT];
#pragma unroll
        for (int q = 0; q < IPT; q++) {
            int o = i0 + q * 256;
            ok[q] = (o < CHUNK);
            ii[q] = base + (ok[q] ? o : 0);
        }
#pragma unroll
        for (int q = 0; q < IPT; q++) {
            load_point(ii[q], xv[q]);
            xx[q] = __ldg(&g_xx[ii[q]]);
        }

        // ---- compute phase: 4 x 8 independent dot chains ----
#pragma unroll
        for (int q = 0; q < IPT; q++) {
            if (!ok[q]) continue;
            const int i = ii[q];
#pragma unroll
            for (int r = 0; r < RPB; r++) {
                float dot = 0.f;
#pragma unroll
                for (int j = 0; j < CC; j++) dot = fmaf(lg[r][j], xv[q][j], dot);
                float key = (ll[r] - 2.0f * dot) + xx[q];
                if (key <= Tf[r]) {
                    int row = r0 + r;
                    int pos = atomicAdd(&g_cnt[row], 1);
                    if (pos < CAP)
                        g_comb[row * CAP + pos] =
                            (((ull)fkey(key)) << 18) | (ull)((i << 1) | Y[i]);
                }
            }
        }
    }
}

// ============================================================
// K4: exact top-K, one warp per row, register-resident.
// 32-iter binary search over the 32-bit KEY, then exact tie
// resolution (jax lower-index-first) via reduce-min over the
// (usually size-1) tie group. 4 warps/block. (8.3us measured.)
// ============================================================
__global__ void __launch_bounds__(32 * FWARPS, 1)
k_final(float* __restrict__ out) {
    const int w    = threadIdx.x >> 5;
    const int lane = threadIdx.x & 31;
    const int row  = blockIdx.x * FWARPS + w;

    int n = g_cnt[row];
    if (n > CAP) n = CAP;

    ull comb[REGN];
    unsigned int key[REGN];
#pragma unroll
    for (int r = 0; r < REGN; r++) {
        int t = lane + 32 * r;
        comb[r] = (t < n) ? __ldg(&g_comb[row * CAP + t]) : ~0ull;
        key[r]  = (unsigned int)(comb[r] >> 18);   // pad -> 0xFFFFFFFF (never selected)
    }

    // 32-iter binary search: smallest key value with count(<=) >= KNN
    unsigned int lo = 0u, hi = 0xFFFFFFFFu;
    for (int it = 0; it < 32; it++) {
        unsigned int mid = lo + ((hi - lo) >> 1);
        unsigned int c = 0;
#pragma unroll
        for (int r = 0; r < REGN; r++) c += (key[r] <= mid) ? 1u : 0u;
        c = __reduce_add_sync(0xffffffffu, c);
        if (c >= KNN) hi = mid; else lo = mid + 1;
    }
    const unsigned int cut = lo;

    // strictly-below counts and Y-sum
    unsigned int cless = 0, ones = 0;
#pragma unroll
    for (int r = 0; r < REGN; r++) {
        if (key[r] < cut) {
            cless++;
            ones += (unsigned int)(comb[r] & 1ull);
        }
    }
    cless = __reduce_add_sync(0xffffffffu, cless);
    ones  = __reduce_add_sync(0xffffffffu, ones);
    int m = KNN - (int)cless;                 // >= 1 members taken from tie group

    // tie group: key == cut; take the m smallest ((i<<1)|Y) (== idx order;
    // idx values are globally distinct, so each reduce-min has a unique owner)
    unsigned int tieMask = 0;
#pragma unroll
    for (int r = 0; r < REGN; r++)
        if (key[r] == cut) tieMask |= (1u << r);
    for (int t = 0; t < m; t++) {
        unsigned int myMin = 0x7FFFFFFFu;
        int myR = -1;
#pragma unroll
        for (int r = 0; r < REGN; r++) {
            if ((tieMask >> r) & 1u) {
                unsigned int v = (unsigned int)(comb[r] & 0x3FFFFull);
                if (v < myMin) { myMin = v; myR = r; }
            }
        }
        unsigned int gmin = __reduce_min_sync(0xffffffffu, myMin);
        ones += gmin & 1u;                    // Y bit of selected element (warp-uniform)
        if (myMin == gmin && myR >= 0) tieMask &= ~(1u << myR);
    }

    if (lane == 0) {
        float v = (float)(2 * (int)ones - KNN);
        float s = (v > 0.f) ? 1.f : ((v < 0.f) ? -1.f : 0.f);
        out[row * 11 + 10] = s * 2.0f * g_maxabs[row];
    }
}

// ============================================================
extern "C" void kernel_launch(void* const* d_in, const int* in_sizes, int n_in,
                              void* d_out, int out_size) {
    const float* x = (const float*)d_in[0];
    const float* W = (const float*)d_in[1];
    const float* b = (const float*)d_in[2];
    const float* X = (const float*)d_in[3];
    const int*   Y = (const int*)d_in[4];
    float* out = (float*)d_out;

    k_front<<<BB + PREPB, 256>>>(x, W, b, X, out);
    k_thresh<<<BB, TTHREADS>>>();
    k_gather<<<(BB / RPB) * NCHUNK, 256>>>(Y);
    k_final<<<BB / FWARPS, 32 * FWARPS>>>(out);
}